// round 14
// baseline (speedup 1.0000x reference)
#include <cuda_runtime.h>
#include <cstdint>

// Math collapse (verified R8-R13): softmax over a size-1 axis == 1.0 exactly,
//   out[b,c,f] = sum_t x[b,t,f]     (context/W/b are dead inputs).
//
// Model from R8-R13 measurements:
//   reads stream at ~7.8TB/s; writes cap at ~1.85-2.5TB/s (per-SM egress,
//   path-invariant). Phase-separated kernels = read + write serial = ~12.7us.
//   The only way under ~8.7us: start writes at ~1us and keep the write path
//   busy while later batches are still being read.
// This kernel: software pipeline over 4 epochs of 8 batches. Epoch e reads
// b in [8e,8e+8) (each b by 32 CTAs x 32KB contiguous slices); CTAs owning
// write-chunks of group e then combine + write those 4MB while epochs e+1..
// continue reading on the other CTAs.

#define B_ 32
#define T_ 512
#define C_ 256
#define F_ 512

static constexpr int F4     = F_ / 4;   // 128 float4 per row
static constexpr int TPB    = 256;
static constexpr int GRID   = 256;
static constexpr int EPOCHS = 4;        // 8 b's per epoch
static constexpr int SUBS   = 32;       // reader CTAs per b
static constexpr int SUBROWS= T_ / SUBS;  // 16 rows per read slice (32KB)

// Scratch (zero-initialized at module load; counters reset every call).
__device__ float4 g_part[B_ * SUBS * F4];   // per-(b,sub) partial rows (2MB)
__device__ float4 g_row [B_ * F4];          // final row per b (64KB)
__device__ int    g_cnt  [B_];              // read-publish count (-> 32)
__device__ int    g_ready[B_];              // final row ready flag
__device__ int    g_done [B_];              // writer-finished count (-> 8)

__device__ __forceinline__ void f4add(float4& a, const float4& b) {
    a.x += b.x; a.y += b.y; a.z += b.z; a.w += b.w;
}

__global__ __launch_bounds__(TPB)
void pipelined_sum_bcast(const float* __restrict__ x, float* __restrict__ out) {
    const int i     = blockIdx.x;            // 0..255
    const int tid   = threadIdx.x;
    const int b_own = i >> 3;                 // write-chunk owner batch
    const int k     = i & 7;                  // chunk id (32 rows of C)
    const int grp   = b_own >> 3;             // pipeline group of my write
    const int f4l   = tid & (F4 - 1);
    const int rh    = tid >> 7;                // 0/1

    __shared__ float4 sm[TPB];                // 4KB

    for (int e = 0; e < EPOCHS; ++e) {
        // ---------------- read + publish: slice of b_r ---------------------
        const int b_r = 8 * e + (i >> 5);      // batch read this epoch
        const int sub = i & 31;                // 16-row sub-slice within b_r
        const float4* xb = reinterpret_cast<const float4*>(x)
                         + ((size_t)b_r * T_ + sub * SUBROWS + rh) * F4 + f4l;
        float4 v0 = __ldg(&xb[ 0 * F4]);
        float4 v1 = __ldg(&xb[ 2 * F4]);
        float4 v2 = __ldg(&xb[ 4 * F4]);
        float4 v3 = __ldg(&xb[ 6 * F4]);
        float4 v4 = __ldg(&xb[ 8 * F4]);
        float4 v5 = __ldg(&xb[10 * F4]);
        float4 v6 = __ldg(&xb[12 * F4]);
        float4 v7 = __ldg(&xb[14 * F4]);
        f4add(v0, v4); f4add(v1, v5); f4add(v2, v6); f4add(v3, v7);
        f4add(v0, v2); f4add(v1, v3);
        f4add(v0, v1);
        sm[tid] = v0;
        __syncthreads();
        if (tid < F4) {
            float4 tot = sm[tid];
            f4add(tot, sm[tid + F4]);
            g_part[((size_t)b_r * SUBS + sub) * F4 + tid] = tot;
        }
        __threadfence();                       // publish partial (release)
        __syncthreads();
        if (tid == 0) atomicAdd(&g_cnt[b_r], 1);
        __syncthreads();

        // ---------------- my write turn? -----------------------------------
        if (grp == e) {
            if (k == 0) {
                // combiner CTA: wait for all 32 publishes of b_own
                if (tid == 0)
                    while (*(volatile int*)&g_cnt[b_own] < SUBS) __nanosleep(32);
                __syncthreads();
                __threadfence();               // acquire partials
                const float4* pp =
                    &g_part[((size_t)b_own * SUBS + rh * 16) * F4 + f4l];
                float4 s = make_float4(0.f, 0.f, 0.f, 0.f);
#pragma unroll
                for (int j = 0; j < 16; ++j)
                    f4add(s, pp[(size_t)j * F4]);
                sm[tid] = s;
                __syncthreads();
                if (tid < F4) {
                    float4 tot = sm[tid];
                    f4add(tot, sm[tid + F4]);
                    g_row[(size_t)b_own * F4 + tid] = tot;
                }
                __threadfence();               // publish final row
                __syncthreads();
                if (tid == 0) *(volatile int*)&g_ready[b_own] = 1;
            } else {
                if (tid == 0)
                    while (*(volatile int*)&g_ready[b_own] == 0) __nanosleep(32);
                __syncthreads();
                __threadfence();               // acquire final row
            }

            // write my 64KB chunk: out[b_own, 32k .. 32k+32, :), contiguous.
            // Each thread holds one column value; 16 register-source STG.128.
            const float4 myval = g_row[(size_t)b_own * F4 + f4l];
            float4* ob = reinterpret_cast<float4*>(out)
                       + ((size_t)b_own * C_ + k * 32) * F4;
#pragma unroll
            for (int j = 0; j < 16; ++j)
                ob[(size_t)j * TPB + tid] = myval;

            __syncthreads();
            if (tid == 0) atomicAdd(&g_done[b_own], 1);
        }
    }

    // ---------------- flag reset for the next graph replay -----------------
    if (k == 0 && tid == 0) {
        while (*(volatile int*)&g_done[b_own] < 8) __nanosleep(32);
        g_cnt[b_own]   = 0;
        g_ready[b_own] = 0;
        g_done[b_own]  = 0;
        __threadfence();
    }
}

extern "C" void kernel_launch(void* const* d_in, const int* in_sizes, int n_in,
                              void* d_out, int out_size) {
    (void)in_sizes; (void)n_in; (void)out_size;
    const float* x = (const float*)d_in[0];   // [B,T,F]; context/W/b dead
    float* out = (float*)d_out;               // [B,C,F]
    // 256 CTAs x 256 threads, 4KB smem: <=2 CTAs/SM needed of 8 possible ->
    // all CTAs co-resident, inter-CTA spins cannot deadlock.
    pipelined_sum_bcast<<<GRID, TPB>>>(x, out);
}

// round 15
// speedup vs baseline: 2.4118x; 2.4118x over previous
#include <cuda_runtime.h>

// Math collapse (verified R8-R14): softmax over a size-1 axis == 1.0 exactly,
//   out[b,c,f] = sum_t x[b,t,f]     (context/W/b are dead inputs).
//
// Write-wall model (R10-R14): 16MB of output = ~8.6us (~1.85TB/s) under STG,
// __stcs, cp.async.bulk, and dual-path — all of which ALLOCATE dirty L2 lines.
// 131072 lines / 184 LTS slices at the observed rate = ~20 cyc/line/slice:
// consistent with an L2 dirty-line-allocation cost. DRAM idle (3%) throughout.
// This round tests the one untried policy: st.global.wt (__stwt) =
// write-through / no-allocate -> skips line allocation, drains to DRAM.

#define B_ 32
#define T_ 512
#define C_ 256
#define F_ 512

static constexpr int F4       = F_ / 4;        // 128 float4 per row
static constexpr int TPB      = 256;
static constexpr int T_CHUNK  = 16;            // rows per K1 CTA
static constexpr int NCHUNK   = T_ / T_CHUNK;  // 32 partial chunks per b
static constexpr int C_CHUNK  = 32;            // rows per K2 CTA
static constexpr int NCCHUNK  = C_ / C_CHUNK;  // 8 K2 CTAs per b

// Partial sums: [B][NCHUNK][F4] float4 (2MB scratch)
__device__ float4 g_part[B_ * NCHUNK * F4];

__device__ __forceinline__ void f4add(float4& a, const float4& b) {
    a.x += b.x; a.y += b.y; a.z += b.z; a.w += b.w;
}

// ---------------- K1: streaming T-reduction (proven ~8TB/s, unchanged) ----
__global__ __launch_bounds__(TPB)
void k1_reduce(const float* __restrict__ x) {
    const int b     = blockIdx.x >> 5;        // /NCHUNK
    const int chunk = blockIdx.x & 31;
    const int f4l   = threadIdx.x & (F4 - 1);
    const int rh    = threadIdx.x >> 7;        // 0 or 1

    const float4* xb = reinterpret_cast<const float4*>(x)
                     + ((size_t)b * T_ + chunk * T_CHUNK + rh) * F4 + f4l;

    float4 v0 = __ldg(&xb[ 0 * F4]);
    float4 v1 = __ldg(&xb[ 2 * F4]);
    float4 v2 = __ldg(&xb[ 4 * F4]);
    float4 v3 = __ldg(&xb[ 6 * F4]);
    float4 v4 = __ldg(&xb[ 8 * F4]);
    float4 v5 = __ldg(&xb[10 * F4]);
    float4 v6 = __ldg(&xb[12 * F4]);
    float4 v7 = __ldg(&xb[14 * F4]);
    f4add(v0, v4); f4add(v1, v5); f4add(v2, v6); f4add(v3, v7);
    f4add(v0, v2); f4add(v1, v3);
    f4add(v0, v1);

    __shared__ float4 sm[TPB];
    sm[threadIdx.x] = v0;
    __syncthreads();
    if (threadIdx.x < F4) {
        float4 tot = sm[threadIdx.x];
        f4add(tot, sm[threadIdx.x + F4]);
        g_part[((size_t)b * NCHUNK + chunk) * F4 + threadIdx.x] = tot;
    }
}

// ---------------- K2: sum partials + WRITE-THROUGH broadcast --------------
// CTA (b, cc) owns out[b, cc*32 .. cc*32+32, :] — contiguous 64KB block.
// 16 independent __stwt (st.global.wt) per thread: no L2 line allocation,
// stream straight toward DRAM.
__global__ __launch_bounds__(TPB)
void k2_broadcast_wt(float* __restrict__ out) {
    const int b   = blockIdx.x >> 3;          // /NCCHUNK
    const int cc  = blockIdx.x & 7;
    const int f4l = threadIdx.x & (F4 - 1);
    const int h   = threadIdx.x >> 7;         // 0/1: each half sums 16 chunks

    const float4* pb = &g_part[((size_t)b * NCHUNK + h * (NCHUNK / 2)) * F4 + f4l];
    float4 s = make_float4(0.f, 0.f, 0.f, 0.f);
#pragma unroll
    for (int k = 0; k < NCHUNK / 2; ++k)
        f4add(s, pb[(size_t)k * F4]);

    __shared__ float4 sm[TPB];
    sm[threadIdx.x] = s;
    __syncthreads();
    if (threadIdx.x < F4) {
        float4 tot = sm[threadIdx.x];
        f4add(tot, sm[threadIdx.x + F4]);
        sm[threadIdx.x] = tot;                // final column sum for (b, f4)
    }
    __syncthreads();

    const float4 myval = sm[f4l];             // value for my column

    // 32 rows x 128 float4 = 4096 stores; 16 per thread, warp-contiguous
    // 512B, consecutive across the 64KB block. Write-through, no-allocate.
    float4* ob = reinterpret_cast<float4*>(out)
               + ((size_t)b * C_ + cc * C_CHUNK) * F4;
#pragma unroll
    for (int k = 0; k < (C_CHUNK * F4) / TPB; ++k) {
        const int idx = (k << 8) + threadIdx.x;    // 0..4095, consecutive
        __stwt(&ob[idx], myval);                   // idx & 127 == f4l
    }
}

extern "C" void kernel_launch(void* const* d_in, const int* in_sizes, int n_in,
                              void* d_out, int out_size) {
    (void)in_sizes; (void)n_in; (void)out_size;
    const float* x = (const float*)d_in[0];   // [B,T,F]; context/W/b dead
    float* out = (float*)d_out;               // [B,C,F]
    k1_reduce<<<B_ * NCHUNK, TPB>>>(x);
    k2_broadcast_wt<<<B_ * NCCHUNK, TPB>>>(out);
}

// round 16
// speedup vs baseline: 2.4177x; 1.0025x over previous
#include <cuda_runtime.h>

// Math collapse (verified R8-R15): softmax over a size-1 axis == 1.0 exactly,
//   out[b,c,f] = sum_t x[b,t,f]     (context/W/b are dead inputs).
//
// Store-wall status: 16MB of output = ~8.6us (~1.85TB/s) under STG/__stcs/
// bulk-DMA/dual-path/__stwt with WARP-CONTIGUOUS addresses (one warp-op = 4
// consecutive 128B lines). ncu shows L2 only 18% busy during that -> limit is
// SM-side store credits vs L2 ack latency. BUT the 8.7us fused champion's
// stores were line-SCATTERED and implied ~3.4TB/s. This round tests exactly
// that: K2 stores the same bytes, same full-line coverage, but each warp-op
// hits 4 lines 2KB apart instead of 4 consecutive lines.

#define B_ 32
#define T_ 512
#define C_ 256
#define F_ 512

static constexpr int F4       = F_ / 4;        // 128 float4 per row
static constexpr int TPB      = 256;
static constexpr int T_CHUNK  = 16;            // rows per K1 CTA
static constexpr int NCHUNK   = T_ / T_CHUNK;  // 32 partial chunks per b
static constexpr int C_CHUNK  = 32;            // rows per K2 CTA
static constexpr int NCCHUNK  = C_ / C_CHUNK;  // 8 K2 CTAs per b

// Partial sums: [B][NCHUNK][F4] float4 (2MB scratch)
__device__ float4 g_part[B_ * NCHUNK * F4];

__device__ __forceinline__ void f4add(float4& a, const float4& b) {
    a.x += b.x; a.y += b.y; a.z += b.z; a.w += b.w;
}

// ---------------- K1: streaming T-reduction (proven ~8TB/s, unchanged) ----
__global__ __launch_bounds__(TPB)
void k1_reduce(const float* __restrict__ x) {
    const int b     = blockIdx.x >> 5;        // /NCHUNK
    const int chunk = blockIdx.x & 31;
    const int f4l   = threadIdx.x & (F4 - 1);
    const int rh    = threadIdx.x >> 7;        // 0 or 1

    const float4* xb = reinterpret_cast<const float4*>(x)
                     + ((size_t)b * T_ + chunk * T_CHUNK + rh) * F4 + f4l;

    float4 v0 = __ldg(&xb[ 0 * F4]);
    float4 v1 = __ldg(&xb[ 2 * F4]);
    float4 v2 = __ldg(&xb[ 4 * F4]);
    float4 v3 = __ldg(&xb[ 6 * F4]);
    float4 v4 = __ldg(&xb[ 8 * F4]);
    float4 v5 = __ldg(&xb[10 * F4]);
    float4 v6 = __ldg(&xb[12 * F4]);
    float4 v7 = __ldg(&xb[14 * F4]);
    f4add(v0, v4); f4add(v1, v5); f4add(v2, v6); f4add(v3, v7);
    f4add(v0, v2); f4add(v1, v3);
    f4add(v0, v1);

    __shared__ float4 sm[TPB];
    sm[threadIdx.x] = v0;
    __syncthreads();
    if (threadIdx.x < F4) {
        float4 tot = sm[threadIdx.x];
        f4add(tot, sm[threadIdx.x + F4]);
        g_part[((size_t)b * NCHUNK + chunk) * F4 + threadIdx.x] = tot;
    }
}

// ---------------- K2: sum partials + LINE-SCATTERED broadcast stores ------
// CTA (b, cc) owns out[b, cc*32 .. cc*32+32, :] (64KB), identical bytes to
// R15. Store mapping: warp w, lane -> (row = 4w + lane/8, colgrp = lane%8).
// One warp-op writes 4 FULL 128B lines spaced 2KB (one row) apart; the 16
// iterations sweep the 16 column-groups. Same line coverage, scattered order.
__global__ __launch_bounds__(TPB)
void k2_scatter(float* __restrict__ out) {
    const int b   = blockIdx.x >> 3;          // /NCCHUNK
    const int cc  = blockIdx.x & 7;
    const int f4l = threadIdx.x & (F4 - 1);
    const int h   = threadIdx.x >> 7;         // 0/1: each half sums 16 chunks

    const float4* pb = &g_part[((size_t)b * NCHUNK + h * (NCHUNK / 2)) * F4 + f4l];
    float4 s = make_float4(0.f, 0.f, 0.f, 0.f);
#pragma unroll
    for (int k = 0; k < NCHUNK / 2; ++k)
        f4add(s, pb[(size_t)k * F4]);

    __shared__ float4 sm[TPB];
    sm[threadIdx.x] = s;
    __syncthreads();
    if (threadIdx.x < F4) {
        float4 tot = sm[threadIdx.x];
        f4add(tot, sm[threadIdx.x + F4]);
        sm[threadIdx.x] = tot;                // final column sums (128 float4)
    }
    __syncthreads();

    const int w   = threadIdx.x >> 5;         // warp 0..7
    const int lid = threadIdx.x & 31;
    const int r4  = lid >> 3;                 // 0..3  (row within warp's 4)
    const int j   = lid & 7;                  // 0..7  (float4 within line)

    // rows 4w+r4 cover 0..31 exactly once; cols k*8+j cover 0..127.
    float4* ob = reinterpret_cast<float4*>(out)
               + ((size_t)b * C_ + cc * C_CHUNK + 4 * w + r4) * F4;
#pragma unroll
    for (int k = 0; k < 16; ++k)
        ob[k * 8 + j] = sm[k * 8 + j];        // 4 scattered full lines / warp-op
}

extern "C" void kernel_launch(void* const* d_in, const int* in_sizes, int n_in,
                              void* d_out, int out_size) {
    (void)in_sizes; (void)n_in; (void)out_size;
    const float* x = (const float*)d_in[0];   // [B,T,F]; context/W/b dead
    float* out = (float*)d_out;               // [B,C,F]
    k1_reduce<<<B_ * NCHUNK, TPB>>>(x);
    k2_scatter<<<B_ * NCCHUNK, TPB>>>(out);
}